// round 4
// baseline (speedup 1.0000x reference)
#include <cuda_runtime.h>

#define BATCH 512
#define SEQ   1024
#define NTAGS 64

typedef unsigned long long ull;

// Scratch (no allocations allowed): per-batch partial results.
__device__ float g_logz[BATCH];
__device__ float g_score[BATCH];

// ---------- packed f32x2 helpers (sm_103a) ----------
__device__ __forceinline__ ull pack2(float a, float b) {
    ull r;
    unsigned ia = __float_as_uint(a), ib = __float_as_uint(b);
    asm("mov.b64 %0, {%1,%2};" : "=l"(r) : "r"(ia), "r"(ib));
    return r;
}
__device__ __forceinline__ void unpack2(ull v, float& a, float& b) {
    unsigned ia, ib;
    asm("mov.b64 {%0,%1}, %2;" : "=r"(ia), "=r"(ib) : "l"(v));
    a = __uint_as_float(ia);
    b = __uint_as_float(ib);
}
__device__ __forceinline__ ull fma2(ull a, ull b, ull c) {
    ull d;
    asm("fma.rn.f32x2 %0, %1, %2, %3;" : "=l"(d) : "l"(a), "l"(b), "l"(c));
    return d;
}
__device__ __forceinline__ ull add2(ull a, ull b) {
    ull d;
    asm("add.rn.f32x2 %0, %1, %2;" : "=l"(d) : "l"(a), "l"(b));
    return d;
}

// ---------- one forward-recurrence step ----------
// c0,c1: centered log-alphas for tags (2*lane, 2*lane+1). Bacc: common base.
// E in registers (exp(T) column pairs). p broadcast through a double-buffered
// shared array of duplicated pairs -> LDS.128 same-address broadcast.
__device__ __forceinline__ void crf_step(
    float2 em2, unsigned int mk, int par,
    float& c0, float& c1, float& Bacc,
    const ull (&Ereg)[NTAGS],
    ulonglong2 (&pb)[2][32], int lane)
{
    float p0 = __expf(c0), p1 = __expf(c1);
    pb[par][lane] = make_ulonglong2(pack2(p0, p0), pack2(p1, p1));
    __syncwarp();
    ull sA = 0ull, sB = 0ull, sC = 0ull, sD = 0ull;  // 4 chains: break FFMA dep chain
#pragma unroll
    for (int i2 = 0; i2 < 32; i2 += 2) {
        ulonglong2 pd0 = pb[par][i2];
        ulonglong2 pd1 = pb[par][i2 + 1];
        sA = fma2(pd0.x, Ereg[2 * i2],     sA);
        sB = fma2(pd0.y, Ereg[2 * i2 + 1], sB);
        sC = fma2(pd1.x, Ereg[2 * i2 + 2], sC);
        sD = fma2(pd1.y, Ereg[2 * i2 + 3], sD);
    }
    ull sP = add2(add2(sA, sB), add2(sC, sD));
    float s0, s1;
    unpack2(sP, s0, s1);
    float n0 = __logf(s0) + em2.x;
    float n1 = __logf(s1) + em2.y;
    float m = __shfl_sync(0xffffffffu, n0, 0);   // recentre on tag 0's new value
    if (mk) { c0 = n0 - m; c1 = n1 - m; Bacc += m; }
}

// ---------- forward algorithm: 1 warp per batch ----------
__global__ void __launch_bounds__(32)
forward_kernel(const float* __restrict__ em,
               const float* __restrict__ startt,
               const float* __restrict__ endt,
               const float* __restrict__ trans,
               const int* __restrict__ mask)
{
    __shared__ ulonglong2 pb[2][32];
    const int b = blockIdx.x;
    const int lane = threadIdx.x;
    const int j0 = 2 * lane, j1 = j0 + 1;

    // E = exp(T): each lane keeps its column pair in registers (128 regs).
    ull Ereg[NTAGS];
#pragma unroll
    for (int i = 0; i < NTAGS; ++i) {
        float2 tv = *(const float2*)(trans + i * NTAGS + j0);
        Ereg[i] = pack2(__expf(tv.x), __expf(tv.y));
    }

    const float2* emp = (const float2*)(em + (size_t)b * SEQ * NTAGS);
    const int* mkp = mask + (size_t)b * SEQ;

    float2 st2 = *(const float2*)(startt + j0);
    float2 e00 = emp[lane];
    float c0 = st2.x + e00.x;
    float c1 = st2.y + e00.y;
    float Bacc;
    { float m = __shfl_sync(0xffffffffu, c0, 0); c0 -= m; c1 -= m; Bacc = m; }

    // Prefetch ring, distance 4 (covers ~600-cyc DRAM latency at ~200 cyc/step).
    float2 f0 = emp[1 * 32 + lane];
    float2 f1 = emp[2 * 32 + lane];
    float2 f2 = emp[3 * 32 + lane];
    float2 f3 = emp[4 * 32 + lane];
    unsigned int m0 = mkp[1], m1 = mkp[2], m2 = mkp[3], m3 = mkp[4];

    // Full groups: t0 = 1,5,...,1013 -> steps 1..1016, always-prefetching 4 ahead.
    for (int t0 = 1; t0 + 7 < SEQ; t0 += 4) {
        float2 e0v = f0, e1v = f1, e2v = f2, e3v = f3;
        unsigned int q0 = m0, q1 = m1, q2 = m2, q3 = m3;
        int tn = t0 + 4;
        f0 = emp[(tn + 0) * 32 + lane]; m0 = mkp[tn + 0];
        f1 = emp[(tn + 1) * 32 + lane]; m1 = mkp[tn + 1];
        f2 = emp[(tn + 2) * 32 + lane]; m2 = mkp[tn + 2];
        f3 = emp[(tn + 3) * 32 + lane]; m3 = mkp[tn + 3];
        crf_step(e0v, q0, 0, c0, c1, Bacc, Ereg, pb, lane);
        crf_step(e1v, q1, 1, c0, c1, Bacc, Ereg, pb, lane);
        crf_step(e2v, q2, 0, c0, c1, Bacc, Ereg, pb, lane);
        crf_step(e3v, q3, 1, c0, c1, Bacc, Ereg, pb, lane);
    }
    // Steps 1017..1020 from the last prefetch, then 1021..1023 loaded directly.
    crf_step(f0, m0, 0, c0, c1, Bacc, Ereg, pb, lane);
    crf_step(f1, m1, 1, c0, c1, Bacc, Ereg, pb, lane);
    crf_step(f2, m2, 0, c0, c1, Bacc, Ereg, pb, lane);
    crf_step(f3, m3, 1, c0, c1, Bacc, Ereg, pb, lane);
    {
        float2 ga = emp[(SEQ - 3) * 32 + lane];
        float2 gb = emp[(SEQ - 2) * 32 + lane];
        float2 gc = emp[(SEQ - 1) * 32 + lane];
        unsigned int qa = mkp[SEQ - 3], qb = mkp[SEQ - 2], qc = mkp[SEQ - 1];
        crf_step(ga, qa, 0, c0, c1, Bacc, Ereg, pb, lane);
        crf_step(gb, qb, 1, c0, c1, Bacc, Ereg, pb, lane);
        crf_step(gc, qc, 0, c0, c1, Bacc, Ereg, pb, lane);
    }

    // log_z = B + logsumexp_j(c_j + end_j)
    float v0 = c0 + endt[j0];
    float v1 = c1 + endt[j1];
    float mx = fmaxf(v0, v1);
#pragma unroll
    for (int o = 16; o > 0; o >>= 1)
        mx = fmaxf(mx, __shfl_xor_sync(0xffffffffu, mx, o));
    float sm = __expf(v0 - mx) + __expf(v1 - mx);
#pragma unroll
    for (int o = 16; o > 0; o >>= 1)
        sm += __shfl_xor_sync(0xffffffffu, sm, o);
    if (lane == 0) g_logz[b] = Bacc + mx + __logf(sm);
}

// ---------- gold-path score: 1 block per batch ----------
__global__ void score_kernel(const float* __restrict__ em,
                             const float* __restrict__ startt,
                             const float* __restrict__ endt,
                             const float* __restrict__ trans,
                             const int* __restrict__ tags,
                             const int* __restrict__ mask)
{
    const int b = blockIdx.x;
    const int tid = threadIdx.x;  // 256
    const int* tg = tags + (size_t)b * SEQ;
    const int* mk = mask + (size_t)b * SEQ;
    const float* e = em + (size_t)b * SEQ * NTAGS;

    float acc = 0.0f;
    int cnt = 0;
    for (int t = tid; t < SEQ; t += 256) {
        int tag = tg[t];
        int mt = mk[t];
        cnt += (mt != 0);
        if (t == 0) {
            acc += startt[tag] + e[tag];
        } else if (mt) {
            int pv = tg[t - 1];
            acc += trans[pv * NTAGS + tag] + e[(size_t)t * NTAGS + tag];
        }
    }
    __shared__ float sacc[256];
    __shared__ int scnt[256];
    sacc[tid] = acc;
    scnt[tid] = cnt;
    __syncthreads();
    for (int o = 128; o > 0; o >>= 1) {
        if (tid < o) { sacc[tid] += sacc[tid + o]; scnt[tid] += scnt[tid + o]; }
        __syncthreads();
    }
    if (tid == 0) {
        int last = tg[scnt[0] - 1];
        g_score[b] = sacc[0] + endt[last];
    }
}

// ---------- deterministic final reduction ----------
__global__ void finalize_kernel(float* __restrict__ out)
{
    __shared__ float s[BATCH];
    int tid = threadIdx.x;
    s[tid] = g_logz[tid] - g_score[tid];
    __syncthreads();
    for (int o = BATCH / 2; o > 0; o >>= 1) {
        if (tid < o) s[tid] += s[tid + o];
        __syncthreads();
    }
    if (tid == 0) out[0] = s[0];
}

extern "C" void kernel_launch(void* const* d_in, const int* in_sizes, int n_in,
                              void* d_out, int out_size)
{
    const float* em      = (const float*)d_in[0];
    const float* startt  = (const float*)d_in[1];
    const float* endt    = (const float*)d_in[2];
    const float* trans   = (const float*)d_in[3];
    const int*   tags    = (const int*)d_in[4];
    const int*   mask    = (const int*)d_in[5];
    float* out = (float*)d_out;

    score_kernel<<<BATCH, 256>>>(em, startt, endt, trans, tags, mask);
    forward_kernel<<<BATCH, 32>>>(em, startt, endt, trans, mask);
    finalize_kernel<<<1, BATCH>>>(out);
}

// round 5
// speedup vs baseline: 1.0221x; 1.0221x over previous
#include <cuda_runtime.h>

#define BATCH 512
#define SEQ   1024
#define NTAGS 64

typedef unsigned long long ull;

__device__ float g_logz[BATCH];
__device__ float g_score[BATCH];

#define L2E 1.4426950408889634f
#define LN2 0.6931471805599453f

// ---------- packed f32x2 + MUFU helpers (sm_103a) ----------
__device__ __forceinline__ ull pack2(float a, float b) {
    ull r;
    unsigned ia = __float_as_uint(a), ib = __float_as_uint(b);
    asm("mov.b64 %0, {%1,%2};" : "=l"(r) : "r"(ia), "r"(ib));
    return r;
}
__device__ __forceinline__ void unpack2(ull v, float& a, float& b) {
    unsigned ia, ib;
    asm("mov.b64 {%0,%1}, %2;" : "=r"(ia), "=r"(ib) : "l"(v));
    a = __uint_as_float(ia);
    b = __uint_as_float(ib);
}
__device__ __forceinline__ ull fma2(ull a, ull b, ull c) {
    ull d;
    asm("fma.rn.f32x2 %0, %1, %2, %3;" : "=l"(d) : "l"(a), "l"(b), "l"(c));
    return d;
}
__device__ __forceinline__ ull add2(ull a, ull b) {
    ull d;
    asm("add.rn.f32x2 %0, %1, %2;" : "=l"(d) : "l"(a), "l"(b));
    return d;
}
__device__ __forceinline__ float ex2f(float x) {
    float r; asm("ex2.approx.f32 %0, %1;" : "=f"(r) : "f"(x)); return r;
}
__device__ __forceinline__ float lg2f(float x) {
    float r; asm("lg2.approx.f32 %0, %1;" : "=f"(r) : "f"(x)); return r;
}

// ---------- one forward-recurrence step (log2 domain) ----------
// Invariant: true_log2_alpha_j = c_j + Bacc.
// msub = lagged recentre value (shfl'd LAST step, so off the critical path).
// em2 is pre-scaled by log2(e). Branchless mask via selects.
__device__ __forceinline__ void crf_step(
    float2 em2, unsigned int mk, int par,
    float& c0, float& c1, float& Bacc, float& msub,
    const ull (&Ereg)[NTAGS],
    ulonglong2 (&pb)[2][32], int lane)
{
    float p0 = ex2f(c0), p1 = ex2f(c1);
    pb[par][lane] = make_ulonglong2(pack2(p0, p0), pack2(p1, p1));
    __syncwarp();
    ull sA = 0ull, sB = 0ull, sC = 0ull, sD = 0ull;  // 4 chains: break FFMA dep chain
#pragma unroll
    for (int i2 = 0; i2 < 32; i2 += 2) {
        ulonglong2 pd0 = pb[par][i2];
        ulonglong2 pd1 = pb[par][i2 + 1];
        sA = fma2(pd0.x, Ereg[2 * i2],     sA);
        sB = fma2(pd0.y, Ereg[2 * i2 + 1], sB);
        sC = fma2(pd1.x, Ereg[2 * i2 + 2], sC);
        sD = fma2(pd1.y, Ereg[2 * i2 + 3], sD);
    }
    ull sP = add2(add2(sA, sB), add2(sC, sD));
    float s0, s1;
    unpack2(sP, s0, s1);
    // n = log2(sum) + em*log2e - lagged_centre
    float n0 = lg2f(s0) + (em2.x - msub);
    float n1 = lg2f(s1) + (em2.y - msub);
    bool u = (mk != 0);
    float nB = Bacc + msub;
    c0   = u ? n0 : c0;     // SEL, no branch
    c1   = u ? n1 : c1;
    Bacc = u ? nB : Bacc;
    // Broadcast next step's centre NOW: its 26-32cyc latency hides under the
    // next step's exp/sync/dot (~120cyc) instead of sitting on the chain.
    msub = __shfl_sync(0xffffffffu, c0, 0);
}

// ---------- forward algorithm: 1 warp per batch ----------
__global__ void __launch_bounds__(32)
forward_kernel(const float* __restrict__ em,
               const float* __restrict__ startt,
               const float* __restrict__ endt,
               const float* __restrict__ trans,
               const int* __restrict__ mask)
{
    __shared__ ulonglong2 pb[2][32];
    const int b = blockIdx.x;
    const int lane = threadIdx.x;
    const int j0 = 2 * lane, j1 = j0 + 1;

    // E = exp(T) (natural): lane keeps its column pair in registers (128 regs).
    ull Ereg[NTAGS];
#pragma unroll
    for (int i = 0; i < NTAGS; ++i) {
        float2 tv = *(const float2*)(trans + i * NTAGS + j0);
        Ereg[i] = pack2(__expf(tv.x), __expf(tv.y));
    }

    const float2* emp = (const float2*)(em + (size_t)b * SEQ * NTAGS);
    const int* mkp = mask + (size_t)b * SEQ;

    float2 st2 = *(const float2*)(startt + j0);
    float2 e00 = emp[lane];
    float c0 = (st2.x + e00.x) * L2E;   // log2 units
    float c1 = (st2.y + e00.y) * L2E;
    float Bacc = 0.0f;
    float msub = __shfl_sync(0xffffffffu, c0, 0);

    // Prefetch ring, distance 4; emissions pre-scaled by log2e off the chain.
    float2 f0 = emp[1 * 32 + lane]; f0.x *= L2E; f0.y *= L2E;
    float2 f1 = emp[2 * 32 + lane]; f1.x *= L2E; f1.y *= L2E;
    float2 f2 = emp[3 * 32 + lane]; f2.x *= L2E; f2.y *= L2E;
    float2 f3 = emp[4 * 32 + lane]; f3.x *= L2E; f3.y *= L2E;
    unsigned int m0 = mkp[1], m1 = mkp[2], m2 = mkp[3], m3 = mkp[4];

    for (int t0 = 1; t0 + 7 < SEQ; t0 += 4) {
        float2 e0v = f0, e1v = f1, e2v = f2, e3v = f3;
        unsigned int q0 = m0, q1 = m1, q2 = m2, q3 = m3;
        int tn = t0 + 4;
        f0 = emp[(tn + 0) * 32 + lane]; f0.x *= L2E; f0.y *= L2E; m0 = mkp[tn + 0];
        f1 = emp[(tn + 1) * 32 + lane]; f1.x *= L2E; f1.y *= L2E; m1 = mkp[tn + 1];
        f2 = emp[(tn + 2) * 32 + lane]; f2.x *= L2E; f2.y *= L2E; m2 = mkp[tn + 2];
        f3 = emp[(tn + 3) * 32 + lane]; f3.x *= L2E; f3.y *= L2E; m3 = mkp[tn + 3];
        crf_step(e0v, q0, 0, c0, c1, Bacc, msub, Ereg, pb, lane);
        crf_step(e1v, q1, 1, c0, c1, Bacc, msub, Ereg, pb, lane);
        crf_step(e2v, q2, 0, c0, c1, Bacc, msub, Ereg, pb, lane);
        crf_step(e3v, q3, 1, c0, c1, Bacc, msub, Ereg, pb, lane);
    }
    crf_step(f0, m0, 0, c0, c1, Bacc, msub, Ereg, pb, lane);
    crf_step(f1, m1, 1, c0, c1, Bacc, msub, Ereg, pb, lane);
    crf_step(f2, m2, 0, c0, c1, Bacc, msub, Ereg, pb, lane);
    crf_step(f3, m3, 1, c0, c1, Bacc, msub, Ereg, pb, lane);
    {
        float2 ga = emp[(SEQ - 3) * 32 + lane]; ga.x *= L2E; ga.y *= L2E;
        float2 gb = emp[(SEQ - 2) * 32 + lane]; gb.x *= L2E; gb.y *= L2E;
        float2 gc = emp[(SEQ - 1) * 32 + lane]; gc.x *= L2E; gc.y *= L2E;
        unsigned int qa = mkp[SEQ - 3], qb = mkp[SEQ - 2], qc = mkp[SEQ - 1];
        crf_step(ga, qa, 0, c0, c1, Bacc, msub, Ereg, pb, lane);
        crf_step(gb, qb, 1, c0, c1, Bacc, msub, Ereg, pb, lane);
        crf_step(gc, qc, 0, c0, c1, Bacc, msub, Ereg, pb, lane);
    }

    // log_z = ln2 * (Bacc + log2sumexp2_j(c_j + end_j*log2e))
    float v0 = c0 + endt[j0] * L2E;
    float v1 = c1 + endt[j1] * L2E;
    float mx = fmaxf(v0, v1);
#pragma unroll
    for (int o = 16; o > 0; o >>= 1)
        mx = fmaxf(mx, __shfl_xor_sync(0xffffffffu, mx, o));
    float sm = ex2f(v0 - mx) + ex2f(v1 - mx);
#pragma unroll
    for (int o = 16; o > 0; o >>= 1)
        sm += __shfl_xor_sync(0xffffffffu, sm, o);
    if (lane == 0) g_logz[b] = LN2 * (Bacc + mx + lg2f(sm));
}

// ---------- gold-path score: 1 block per batch ----------
__global__ void score_kernel(const float* __restrict__ em,
                             const float* __restrict__ startt,
                             const float* __restrict__ endt,
                             const float* __restrict__ trans,
                             const int* __restrict__ tags,
                             const int* __restrict__ mask)
{
    const int b = blockIdx.x;
    const int tid = threadIdx.x;  // 256
    const int* tg = tags + (size_t)b * SEQ;
    const int* mk = mask + (size_t)b * SEQ;
    const float* e = em + (size_t)b * SEQ * NTAGS;

    float acc = 0.0f;
    int cnt = 0;
    for (int t = tid; t < SEQ; t += 256) {
        int tag = tg[t];
        int mt = mk[t];
        cnt += (mt != 0);
        if (t == 0) {
            acc += startt[tag] + e[tag];
        } else if (mt) {
            int pv = tg[t - 1];
            acc += trans[pv * NTAGS + tag] + e[(size_t)t * NTAGS + tag];
        }
    }
    __shared__ float sacc[256];
    __shared__ int scnt[256];
    sacc[tid] = acc;
    scnt[tid] = cnt;
    __syncthreads();
    for (int o = 128; o > 0; o >>= 1) {
        if (tid < o) { sacc[tid] += sacc[tid + o]; scnt[tid] += scnt[tid + o]; }
        __syncthreads();
    }
    if (tid == 0) {
        int last = tg[scnt[0] - 1];
        g_score[b] = sacc[0] + endt[last];
    }
}

// ---------- deterministic final reduction ----------
__global__ void finalize_kernel(float* __restrict__ out)
{
    __shared__ float s[BATCH];
    int tid = threadIdx.x;
    s[tid] = g_logz[tid] - g_score[tid];
    __syncthreads();
    for (int o = BATCH / 2; o > 0; o >>= 1) {
        if (tid < o) s[tid] += s[tid + o];
        __syncthreads();
    }
    if (tid == 0) out[0] = s[0];
}

extern "C" void kernel_launch(void* const* d_in, const int* in_sizes, int n_in,
                              void* d_out, int out_size)
{
    const float* em      = (const float*)d_in[0];
    const float* startt  = (const float*)d_in[1];
    const float* endt    = (const float*)d_in[2];
    const float* trans   = (const float*)d_in[3];
    const int*   tags    = (const int*)d_in[4];
    const int*   mask    = (const int*)d_in[5];
    float* out = (float*)d_out;

    // forward first: lets the bounded ncu capture window land on it.
    forward_kernel<<<BATCH, 32>>>(em, startt, endt, trans, mask);
    score_kernel<<<BATCH, 256>>>(em, startt, endt, trans, tags, mask);
    finalize_kernel<<<1, BATCH>>>(out);
}

// round 9
// speedup vs baseline: 1.5110x; 1.4783x over previous
#include <cuda_runtime.h>

#define BATCH 512
#define SEQ   1024
#define NTAGS 64

#define L2E 1.4426950408889634f
#define LN2 0.6931471805599453f

typedef unsigned long long ull;

__device__ float g_logz[BATCH];
__device__ float g_score[BATCH];

// ---------- packed f32x2 + MUFU helpers (sm_103a) ----------
__device__ __forceinline__ ull pack2(float a, float b) {
    ull r;
    unsigned ia = __float_as_uint(a), ib = __float_as_uint(b);
    asm("mov.b64 %0, {%1,%2};" : "=l"(r) : "r"(ia), "r"(ib));
    return r;
}
__device__ __forceinline__ void unpack2(ull v, float& a, float& b) {
    unsigned ia, ib;
    asm("mov.b64 {%0,%1}, %2;" : "=r"(ia), "=r"(ib) : "l"(v));
    a = __uint_as_float(ia);
    b = __uint_as_float(ib);
}
__device__ __forceinline__ ull fma2(ull a, ull b, ull c) {
    ull d;
    asm("fma.rn.f32x2 %0, %1, %2, %3;" : "=l"(d) : "l"(a), "l"(b), "l"(c));
    return d;
}
__device__ __forceinline__ ull add2(ull a, ull b) {
    ull d;
    asm("add.rn.f32x2 %0, %1, %2;" : "=l"(d) : "l"(a), "l"(b));
    return d;
}
__device__ __forceinline__ float ex2f(float x) {
    float r; asm("ex2.approx.f32 %0, %1;" : "=f"(r) : "f"(x)); return r;
}
__device__ __forceinline__ float lg2f(float x) {
    float r; asm("lg2.approx.f32 %0, %1;" : "=f"(r) : "f"(x)); return r;
}

// ---------- one forward-recurrence step (log2 domain, 128 threads/batch) ----
// Thread layout: tag j = tid>>1; half = tid&1 sums i in [32*half, 32*half+32).
// Invariant at step start: true_log2_alpha_j = c_j + Bacc (identical Bacc on
// all threads; c duplicated across each tag's thread pair).
// One __syncthreads per step; pbuf/msub double-buffered (par alternates).
__device__ __forceinline__ void crf_step(
    float emv, int mk, int par,
    float& c, float& Bacc,
    const ull (&Epair)[16],
    float (&pbuf)[2][68], float (&msub_s)[2],
    int tid, int half, int pidx)
{
    float p = ex2f(c);
    if (half == 0) pbuf[par][pidx] = p;   // one writer per tag, conflict-free
    if (tid == 0) msub_s[par] = c;        // current centre (tag 0)
    __syncthreads();
    float msub = msub_s[par];
    // 8 batched LDS.128 (p as packed f32x2 pairs), 16 FFMA2 in 4 chains.
    const ulonglong2* pv =
        reinterpret_cast<const ulonglong2*>(&pbuf[par][half ? 36 : 0]);
    ull sA = 0ull, sB = 0ull, sC = 0ull, sD = 0ull;
#pragma unroll
    for (int k = 0; k < 8; k += 2) {
        ulonglong2 qa = pv[k];
        ulonglong2 qb = pv[k + 1];
        sA = fma2(qa.x, Epair[2 * k],     sA);
        sB = fma2(qa.y, Epair[2 * k + 1], sB);
        sC = fma2(qb.x, Epair[2 * k + 2], sC);
        sD = fma2(qb.y, Epair[2 * k + 3], sD);
    }
    ull sP = add2(add2(sA, sB), add2(sC, sD));
    float lo, hi;
    unpack2(sP, lo, hi);
    float s = lo + hi;
    s += __shfl_xor_sync(0xffffffffu, s, 1);   // combine the two i-halves
    float n = lg2f(s) + (emv - msub);
    bool u = (mk != 0);
    c    = u ? n : c;                          // SEL, no branch
    Bacc = u ? (Bacc + msub) : Bacc;
}

// ---------- forward algorithm: 4 warps per batch ----------
__global__ void __launch_bounds__(128)
forward_kernel(const float* __restrict__ em,
               const float* __restrict__ startt,
               const float* __restrict__ endt,
               const float* __restrict__ trans,
               const int* __restrict__ mask)
{
    __shared__ __align__(16) float pbuf[2][68];   // halves at [0..31] and [36..67]
    __shared__ float msub_s[2];
    __shared__ float vred[NTAGS];

    const int b = blockIdx.x;
    const int tid = threadIdx.x;
    const int j = tid >> 1;
    const int half = tid & 1;
    const int ibase = half << 5;
    const int pidx = j + ((j >= 32) ? 4 : 0);

    // E slice: exp(T[i][j]) for this thread's 32 i-values, packed f32x2 (32 regs).
    ull Epair[16];
#pragma unroll
    for (int k = 0; k < 16; ++k) {
        float ea = __expf(trans[(ibase + 2 * k)     * NTAGS + j]);
        float eb = __expf(trans[(ibase + 2 * k + 1) * NTAGS + j]);
        Epair[k] = pack2(ea, eb);
    }

    const float* emB = em + (size_t)b * SEQ * NTAGS + j;
    const int* mkp = mask + (size_t)b * SEQ;

    float c = (startt[j] + emB[0]) * L2E;   // log2 units
    float Bacc = 0.0f;

    // Prefetch ring, distance 4 (scalar em + mask; off the chain).
    float f0 = emB[(size_t)1 * NTAGS] * L2E;
    float f1 = emB[(size_t)2 * NTAGS] * L2E;
    float f2 = emB[(size_t)3 * NTAGS] * L2E;
    float f3 = emB[(size_t)4 * NTAGS] * L2E;
    int m0 = mkp[1], m1 = mkp[2], m2 = mkp[3], m3 = mkp[4];

    for (int t0 = 1; t0 + 7 < SEQ; t0 += 4) {
        float e0 = f0, e1 = f1, e2 = f2, e3 = f3;
        int q0 = m0, q1 = m1, q2 = m2, q3 = m3;
        int tn = t0 + 4;
        f0 = emB[(size_t)(tn + 0) * NTAGS] * L2E; m0 = mkp[tn + 0];
        f1 = emB[(size_t)(tn + 1) * NTAGS] * L2E; m1 = mkp[tn + 1];
        f2 = emB[(size_t)(tn + 2) * NTAGS] * L2E; m2 = mkp[tn + 2];
        f3 = emB[(size_t)(tn + 3) * NTAGS] * L2E; m3 = mkp[tn + 3];
        crf_step(e0, q0, 0, c, Bacc, Epair, pbuf, msub_s, tid, half, pidx);
        crf_step(e1, q1, 1, c, Bacc, Epair, pbuf, msub_s, tid, half, pidx);
        crf_step(e2, q2, 0, c, Bacc, Epair, pbuf, msub_s, tid, half, pidx);
        crf_step(e3, q3, 1, c, Bacc, Epair, pbuf, msub_s, tid, half, pidx);
    }
    crf_step(f0, m0, 0, c, Bacc, Epair, pbuf, msub_s, tid, half, pidx);
    crf_step(f1, m1, 1, c, Bacc, Epair, pbuf, msub_s, tid, half, pidx);
    crf_step(f2, m2, 0, c, Bacc, Epair, pbuf, msub_s, tid, half, pidx);
    crf_step(f3, m3, 1, c, Bacc, Epair, pbuf, msub_s, tid, half, pidx);
    {
        float ga = emB[(size_t)(SEQ - 3) * NTAGS] * L2E;
        float gb = emB[(size_t)(SEQ - 2) * NTAGS] * L2E;
        float gc = emB[(size_t)(SEQ - 1) * NTAGS] * L2E;
        int qa = mkp[SEQ - 3], qb = mkp[SEQ - 2], qc = mkp[SEQ - 1];
        crf_step(ga, qa, 0, c, Bacc, Epair, pbuf, msub_s, tid, half, pidx);
        crf_step(gb, qb, 1, c, Bacc, Epair, pbuf, msub_s, tid, half, pidx);
        crf_step(gc, qc, 0, c, Bacc, Epair, pbuf, msub_s, tid, half, pidx);
    }

    // log_z = ln2 * (Bacc + log2sumexp2_j(c_j + end_j*log2e))
    float v = c + endt[j] * L2E;
    if (half == 0) vred[j] = v;
    __syncthreads();
    if (tid < 32) {
        float a = vred[tid];
        float d = vred[tid + 32];
        float mx = fmaxf(a, d);
#pragma unroll
        for (int o = 16; o > 0; o >>= 1)
            mx = fmaxf(mx, __shfl_xor_sync(0xffffffffu, mx, o));
        float sm = ex2f(a - mx) + ex2f(d - mx);
#pragma unroll
        for (int o = 16; o > 0; o >>= 1)
            sm += __shfl_xor_sync(0xffffffffu, sm, o);
        if (tid == 0) g_logz[b] = LN2 * (Bacc + mx + lg2f(sm));
    }
}

// ---------- gold-path score: 1 block per batch ----------
__global__ void score_kernel(const float* __restrict__ em,
                             const float* __restrict__ startt,
                             const float* __restrict__ endt,
                             const float* __restrict__ trans,
                             const int* __restrict__ tags,
                             const int* __restrict__ mask)
{
    const int b = blockIdx.x;
    const int tid = threadIdx.x;  // 256
    const int* tg = tags + (size_t)b * SEQ;
    const int* mk = mask + (size_t)b * SEQ;
    const float* e = em + (size_t)b * SEQ * NTAGS;

    float acc = 0.0f;
    int cnt = 0;
    for (int t = tid; t < SEQ; t += 256) {
        int tag = tg[t];
        int mt = mk[t];
        cnt += (mt != 0);
        if (t == 0) {
            acc += startt[tag] + e[tag];
        } else if (mt) {
            int pv = tg[t - 1];
            acc += trans[pv * NTAGS + tag] + e[(size_t)t * NTAGS + tag];
        }
    }
    __shared__ float sacc[256];
    __shared__ int scnt[256];
    sacc[tid] = acc;
    scnt[tid] = cnt;
    __syncthreads();
    for (int o = 128; o > 0; o >>= 1) {
        if (tid < o) { sacc[tid] += sacc[tid + o]; scnt[tid] += scnt[tid + o]; }
        __syncthreads();
    }
    if (tid == 0) {
        int last = tg[scnt[0] - 1];
        g_score[b] = sacc[0] + endt[last];
    }
}

// ---------- deterministic final reduction ----------
__global__ void finalize_kernel(float* __restrict__ out)
{
    __shared__ float s[BATCH];
    int tid = threadIdx.x;
    s[tid] = g_logz[tid] - g_score[tid];
    __syncthreads();
    for (int o = BATCH / 2; o > 0; o >>= 1) {
        if (tid < o) s[tid] += s[tid + o];
        __syncthreads();
    }
    if (tid == 0) out[0] = s[0];
}

extern "C" void kernel_launch(void* const* d_in, const int* in_sizes, int n_in,
                              void* d_out, int out_size)
{
    const float* em      = (const float*)d_in[0];
    const float* startt  = (const float*)d_in[1];
    const float* endt    = (const float*)d_in[2];
    const float* trans   = (const float*)d_in[3];
    const int*   tags    = (const int*)d_in[4];
    const int*   mask    = (const int*)d_in[5];
    float* out = (float*)d_out;

    // forward first: keeps the bounded ncu capture window on it.
    forward_kernel<<<BATCH, 128>>>(em, startt, endt, trans, mask);
    score_kernel<<<BATCH, 256>>>(em, startt, endt, trans, tags, mask);
    finalize_kernel<<<1, BATCH>>>(out);
}

// round 10
// speedup vs baseline: 2.5789x; 1.7068x over previous
#include <cuda_runtime.h>

#define BATCH 512
#define SEQ   1024
#define NTAGS 64

#define L2E 1.4426950408889634f
#define LN2 0.6931471805599453f

typedef unsigned long long ull;

__device__ float g_logz[BATCH];
__device__ float g_score[BATCH];

// ---------- packed f32x2 + MUFU helpers (sm_103a) ----------
__device__ __forceinline__ ull pack2(float a, float b) {
    ull r;
    unsigned ia = __float_as_uint(a), ib = __float_as_uint(b);
    asm("mov.b64 %0, {%1,%2};" : "=l"(r) : "r"(ia), "r"(ib));
    return r;
}
__device__ __forceinline__ void unpack2(ull v, float& a, float& b) {
    unsigned ia, ib;
    asm("mov.b64 {%0,%1}, %2;" : "=r"(ia), "=r"(ib) : "l"(v));
    a = __uint_as_float(ia);
    b = __uint_as_float(ib);
}
__device__ __forceinline__ ull fma2(ull a, ull b, ull c) {
    ull d;
    asm("fma.rn.f32x2 %0, %1, %2, %3;" : "=l"(d) : "l"(a), "l"(b), "l"(c));
    return d;
}
__device__ __forceinline__ ull add2(ull a, ull b) {
    ull d;
    asm("add.rn.f32x2 %0, %1, %2;" : "=l"(d) : "l"(a), "l"(b));
    return d;
}
__device__ __forceinline__ float ex2f(float x) {
    float r; asm("ex2.approx.f32 %0, %1;" : "=f"(r) : "f"(x)); return r;
}
__device__ __forceinline__ float lg2f(float x) {
    float r; asm("lg2.approx.f32 %0, %1;" : "=f"(r) : "f"(x)); return r;
}
__device__ __forceinline__ float rcpf(float x) {
    float r; asm("rcp.approx.f32 %0, %1;" : "=f"(r) : "f"(x)); return r;
}

// ---------- one forward-recurrence step (probability domain) ----------
// 64 threads/batch, thread tid owns tag j = tid.
// Invariant at step start: true_log2_alpha_j = lg2(a_j) + Bacc  (Bacc uniform).
// eem = exp(em) precomputed at prefetch (off-chain). a0 (normalizer), its
// rcp and lg2 all run in parallel with the dot. No branches: SEL only.
// One __syncthreads per step; pbuf double-buffered via par.
__device__ __forceinline__ void crf_step(
    float eem, int mk, int par,
    float& a, float& Bacc,
    const ull (&Epair)[32],
    float (&pbuf)[2][64],
    int tid)
{
    pbuf[par][tid] = a;            // unconditional: one writer per address
    __syncthreads();
    float a0 = pbuf[par][0];       // scalar broadcast LDS (parallel to vector loads)
    const ulonglong2* pv = reinterpret_cast<const ulonglong2*>(&pbuf[par][0]);
    ull sA = 0ull, sB = 0ull, sC = 0ull, sD = 0ull;   // 4 chains
#pragma unroll
    for (int k = 0; k < 16; k += 2) {
        ulonglong2 qa = pv[k];
        ulonglong2 qb = pv[k + 1];
        sA = fma2(qa.x, Epair[2 * k],     sA);
        sB = fma2(qa.y, Epair[2 * k + 1], sB);
        sC = fma2(qb.x, Epair[2 * k + 2], sC);
        sD = fma2(qb.y, Epair[2 * k + 3], sD);
    }
    float ra0 = rcpf(a0);          // both off the dot's critical path
    float la0 = lg2f(a0);
    ull sP = add2(add2(sA, sB), add2(sC, sD));
    float lo, hi;
    unpack2(sP, lo, hi);
    float s = lo + hi;
    float anew = s * (eem * ra0);  // eem*ra0 folds while dot finishes
    bool u = (mk != 0);
    a    = u ? anew : a;           // SEL
    Bacc = u ? (Bacc + la0) : Bacc;
}

// ---------- forward algorithm: 2 warps per batch ----------
__global__ void __launch_bounds__(64)
forward_kernel(const float* __restrict__ em,
               const float* __restrict__ startt,
               const float* __restrict__ endt,
               const float* __restrict__ trans,
               const int* __restrict__ mask)
{
    __shared__ __align__(16) float pbuf[2][64];
    __shared__ float vred[NTAGS];

    const int b = blockIdx.x;
    const int tid = threadIdx.x;   // == tag j
    const int j = tid;

    // E column for tag j: exp(T[i][j]), i=0..63, packed f32x2 (64 regs).
    ull Epair[32];
#pragma unroll
    for (int k = 0; k < 32; ++k) {
        float ea = __expf(trans[(2 * k)     * NTAGS + j]);
        float eb = __expf(trans[(2 * k + 1) * NTAGS + j]);
        Epair[k] = pack2(ea, eb);
    }

    const float* emB = em + (size_t)b * SEQ * NTAGS + j;
    const int* mkp = mask + (size_t)b * SEQ;

    float a = ex2f((startt[j] + emB[0]) * L2E);   // prob domain
    float Bacc = 0.0f;

    // Prefetch ring, distance 4: exp(em) computed here, off the chain.
    float f0 = ex2f(emB[(size_t)1 * NTAGS] * L2E);
    float f1 = ex2f(emB[(size_t)2 * NTAGS] * L2E);
    float f2 = ex2f(emB[(size_t)3 * NTAGS] * L2E);
    float f3 = ex2f(emB[(size_t)4 * NTAGS] * L2E);
    int m0 = mkp[1], m1 = mkp[2], m2 = mkp[3], m3 = mkp[4];

    for (int t0 = 1; t0 + 7 < SEQ; t0 += 4) {
        float e0 = f0, e1 = f1, e2 = f2, e3 = f3;
        int q0 = m0, q1 = m1, q2 = m2, q3 = m3;
        int tn = t0 + 4;
        f0 = ex2f(emB[(size_t)(tn + 0) * NTAGS] * L2E); m0 = mkp[tn + 0];
        f1 = ex2f(emB[(size_t)(tn + 1) * NTAGS] * L2E); m1 = mkp[tn + 1];
        f2 = ex2f(emB[(size_t)(tn + 2) * NTAGS] * L2E); m2 = mkp[tn + 2];
        f3 = ex2f(emB[(size_t)(tn + 3) * NTAGS] * L2E); m3 = mkp[tn + 3];
        crf_step(e0, q0, 0, a, Bacc, Epair, pbuf, tid);
        crf_step(e1, q1, 1, a, Bacc, Epair, pbuf, tid);
        crf_step(e2, q2, 0, a, Bacc, Epair, pbuf, tid);
        crf_step(e3, q3, 1, a, Bacc, Epair, pbuf, tid);
    }
    crf_step(f0, m0, 0, a, Bacc, Epair, pbuf, tid);
    crf_step(f1, m1, 1, a, Bacc, Epair, pbuf, tid);
    crf_step(f2, m2, 0, a, Bacc, Epair, pbuf, tid);
    crf_step(f3, m3, 1, a, Bacc, Epair, pbuf, tid);
    {
        float ga = ex2f(emB[(size_t)(SEQ - 3) * NTAGS] * L2E);
        float gb = ex2f(emB[(size_t)(SEQ - 2) * NTAGS] * L2E);
        float gc = ex2f(emB[(size_t)(SEQ - 1) * NTAGS] * L2E);
        int qa = mkp[SEQ - 3], qb = mkp[SEQ - 2], qc = mkp[SEQ - 1];
        crf_step(ga, qa, 0, a, Bacc, Epair, pbuf, tid);
        crf_step(gb, qb, 1, a, Bacc, Epair, pbuf, tid);
        crf_step(gc, qc, 0, a, Bacc, Epair, pbuf, tid);
    }

    // log_z = ln2 * (Bacc + lg2(sum_j a_j * exp(end_j)))  (all a_j > 0, bounded)
    vred[j] = a * __expf(endt[j]);
    __syncthreads();
    if (tid < 32) {
        float s = vred[tid] + vred[tid + 32];
#pragma unroll
        for (int o = 16; o > 0; o >>= 1)
            s += __shfl_xor_sync(0xffffffffu, s, o);
        if (tid == 0) g_logz[b] = LN2 * (Bacc + lg2f(s));
    }
}

// ---------- gold-path score: 1 block per batch ----------
__global__ void score_kernel(const float* __restrict__ em,
                             const float* __restrict__ startt,
                             const float* __restrict__ endt,
                             const float* __restrict__ trans,
                             const int* __restrict__ tags,
                             const int* __restrict__ mask)
{
    const int b = blockIdx.x;
    const int tid = threadIdx.x;  // 256
    const int* tg = tags + (size_t)b * SEQ;
    const int* mk = mask + (size_t)b * SEQ;
    const float* e = em + (size_t)b * SEQ * NTAGS;

    float acc = 0.0f;
    int cnt = 0;
    for (int t = tid; t < SEQ; t += 256) {
        int tag = tg[t];
        int mt = mk[t];
        cnt += (mt != 0);
        if (t == 0) {
            acc += startt[tag] + e[tag];
        } else if (mt) {
            int pv = tg[t - 1];
            acc += trans[pv * NTAGS + tag] + e[(size_t)t * NTAGS + tag];
        }
    }
    __shared__ float sacc[256];
    __shared__ int scnt[256];
    sacc[tid] = acc;
    scnt[tid] = cnt;
    __syncthreads();
    for (int o = 128; o > 0; o >>= 1) {
        if (tid < o) { sacc[tid] += sacc[tid + o]; scnt[tid] += scnt[tid + o]; }
        __syncthreads();
    }
    if (tid == 0) {
        int last = tg[scnt[0] - 1];
        g_score[b] = sacc[0] + endt[last];
    }
}

// ---------- deterministic final reduction ----------
__global__ void finalize_kernel(float* __restrict__ out)
{
    __shared__ float s[BATCH];
    int tid = threadIdx.x;
    s[tid] = g_logz[tid] - g_score[tid];
    __syncthreads();
    for (int o = BATCH / 2; o > 0; o >>= 1) {
        if (tid < o) s[tid] += s[tid + o];
        __syncthreads();
    }
    if (tid == 0) out[0] = s[0];
}

extern "C" void kernel_launch(void* const* d_in, const int* in_sizes, int n_in,
                              void* d_out, int out_size)
{
    const float* em      = (const float*)d_in[0];
    const float* startt  = (const float*)d_in[1];
    const float* endt    = (const float*)d_in[2];
    const float* trans   = (const float*)d_in[3];
    const int*   tags    = (const int*)d_in[4];
    const int*   mask    = (const int*)d_in[5];
    float* out = (float*)d_out;

    // forward first: keeps the bounded ncu capture window on it.
    forward_kernel<<<BATCH, 64>>>(em, startt, endt, trans, mask);
    score_kernel<<<BATCH, 256>>>(em, startt, endt, trans, tags, mask);
    finalize_kernel<<<1, BATCH>>>(out);
}